// round 1
// baseline (speedup 1.0000x reference)
#include <cuda_runtime.h>

#define N_NODES 8192
#define IN_F    256
#define OUT_F   128
#define ALPHA   0.2f

// ---------------- device scratch (no allocations allowed) ----------------
__device__ float g_h [N_NODES * OUT_F];
__device__ float g_s1[N_NODES], g_s2[N_NODES];
__device__ float g_E1[N_NODES], g_E2[N_NODES];
__device__ float g_F1[N_NODES], g_F2[N_NODES];

// ---------------- packed f32x2 helpers (sm_103a) ----------------
__device__ __forceinline__ unsigned long long pack_dup(float v) {
    unsigned long long r;
    asm("mov.b64 %0, {%1, %1};" : "=l"(r) : "f"(v));
    return r;
}
__device__ __forceinline__ void fma2(unsigned long long &d,
                                     unsigned long long a_,
                                     unsigned long long b_) {
    asm("fma.rn.f32x2 %0, %1, %2, %0;" : "+l"(d) : "l"(a_), "l"(b_));
}
__device__ __forceinline__ void unpack2(unsigned long long v, float &lo, float &hi) {
    asm("mov.b64 {%0, %1}, %2;" : "=f"(lo), "=f"(hi) : "l"(v));
}

// ================= Kernel 1: h = x @ W  (8192x256 @ 256x128) =================
__global__ void __launch_bounds__(256) h_gemm_kernel(const float* __restrict__ x,
                                                     const float* __restrict__ W) {
    __shared__ float xs[64][32];
    __shared__ __align__(16) float Ws[32][OUT_F];

    const int tid = threadIdx.x;
    const int tx  = tid & 15;   // 16 col groups of 8
    const int ty  = tid >> 4;   // 16 row groups of 4
    const int m0  = blockIdx.x * 64;

    float acc[4][8];
    #pragma unroll
    for (int r = 0; r < 4; r++)
        #pragma unroll
        for (int c = 0; c < 8; c++) acc[r][c] = 0.f;

    for (int kt = 0; kt < IN_F; kt += 32) {
        #pragma unroll
        for (int i = tid; i < 64 * 32; i += 256)
            xs[i >> 5][i & 31] = x[(size_t)(m0 + (i >> 5)) * IN_F + kt + (i & 31)];
        #pragma unroll
        for (int i = tid * 4; i < 32 * OUT_F; i += 256 * 4)
            *(float4*)&Ws[i >> 7][i & 127] =
                *(const float4*)&W[(size_t)(kt + (i >> 7)) * OUT_F + (i & 127)];
        __syncthreads();

        #pragma unroll 8
        for (int kk = 0; kk < 32; kk++) {
            float b[8];
            *(float4*)&b[0] = *(const float4*)&Ws[kk][tx * 8];
            *(float4*)&b[4] = *(const float4*)&Ws[kk][tx * 8 + 4];
            #pragma unroll
            for (int r = 0; r < 4; r++) {
                float av = xs[ty * 4 + r][kk];
                #pragma unroll
                for (int c = 0; c < 8; c++) acc[r][c] = fmaf(av, b[c], acc[r][c]);
            }
        }
        __syncthreads();
    }

    #pragma unroll
    for (int r = 0; r < 4; r++)
        #pragma unroll
        for (int c = 0; c < 8; c++)
            g_h[(size_t)(m0 + ty * 4 + r) * OUT_F + tx * 8 + c] = acc[r][c];
}

// ====== Kernel 2: s1,s2 per node + factorized exponentials E/F ======
__global__ void __launch_bounds__(256) s_kernel(const float* __restrict__ a) {
    int node = (blockIdx.x * blockDim.x + threadIdx.x) >> 5;
    int lane = threadIdx.x & 31;
    if (node >= N_NODES) return;

    float s1 = 0.f, s2 = 0.f;
    #pragma unroll
    for (int c = lane; c < OUT_F; c += 32) {
        float hv = g_h[(size_t)node * OUT_F + c];
        s1 = fmaf(hv, __ldg(&a[c]),          s1);
        s2 = fmaf(hv, __ldg(&a[OUT_F + c]),  s2);
    }
    #pragma unroll
    for (int o = 16; o; o >>= 1) {
        s1 += __shfl_xor_sync(0xffffffffu, s1, o);
        s2 += __shfl_xor_sync(0xffffffffu, s2, o);
    }
    if (lane == 0) {
        g_s1[node] = s1;              g_s2[node] = s2;
        g_E1[node] = expf(s1);        g_E2[node] = expf(s2);
        g_F1[node] = expf(ALPHA * s1); g_F2[node] = expf(ALPHA * s2);
    }
}

// ====== Kernel 3: fused masked-softmax attention @ h  ======
// Per CTA: 32 output rows. Stream 32-wide j tiles: build P tile (factorized
// exp + adj mask) in SMEM, accumulate Z, register-blocked f32x2 GEMM P@h.
__global__ void __launch_bounds__(128) gat_main_kernel(const float* __restrict__ adj,
                                                       float* __restrict__ out) {
    const int BM = 32, BK = 32;
    __shared__ float Ps[BM][BK + 1];                 // +1 pad: conflict-free Z sums
    __shared__ __align__(16) float hs[BK][OUT_F];
    __shared__ float Zs[BM], s1s[BM], E1s[BM], F1s[BM];

    const int tid = threadIdx.x;
    const int tx  = tid & 15;    // 16 col groups: cols [tx*4, tx*4+4) and [64+tx*4, ...)
    const int ty  = tid >> 4;    // 8 row groups of 4
    const int m0  = blockIdx.x * BM;

    if (tid < BM) {
        Zs[tid]  = 0.f;
        s1s[tid] = g_s1[m0 + tid];
        E1s[tid] = g_E1[m0 + tid];
        F1s[tid] = g_F1[m0 + tid];
    }
    __syncthreads();

    unsigned long long acc[4][4];
    #pragma unroll
    for (int r = 0; r < 4; r++)
        #pragma unroll
        for (int p = 0; p < 4; p++) acc[r][p] = 0ull;

    const int kcol  = tid & 31;          // column within tile (coalesced adj reads)
    const int mrow0 = (tid >> 5) * 8;    // 8 rows per thread

    for (int j0 = 0; j0 < N_NODES; j0 += BK) {
        // --- load h tile (BK x 128 fp32) ---
        #pragma unroll
        for (int i = tid * 4; i < BK * OUT_F; i += 128 * 4)
            *(float4*)&hs[i >> 7][i & 127] =
                *(const float4*)&g_h[(size_t)(j0 + (i >> 7)) * OUT_F + (i & 127)];

        // --- build P tile: factorized exp, adj mask ---
        {
            const int j = j0 + kcol;
            const float s2v = __ldg(&g_s2[j]);
            const float E2v = __ldg(&g_E2[j]);
            const float F2v = __ldg(&g_F2[j]);
            const float* adjp = adj + (size_t)(m0 + mrow0) * N_NODES + j;
            #pragma unroll
            for (int s = 0; s < 8; s++) {
                const int m = mrow0 + s;
                float av = __ldg(&adjp[(size_t)s * N_NODES]);
                float t  = s1s[m] + s2v;
                float e  = (t >= 0.f) ? (E1s[m] * E2v) : (F1s[m] * F2v);
                Ps[m][kcol] = (av > 0.f) ? e : 0.f;
            }
        }
        __syncthreads();

        // --- Z row sums (one thread per row; padded rows -> no bank conflicts) ---
        if (tid < BM) {
            float z = 0.f;
            #pragma unroll
            for (int k = 0; k < BK; k++) z += Ps[tid][k];
            Zs[tid] += z;
        }

        // --- register-blocked P@h with packed f32x2 FMA ---
        #pragma unroll 4
        for (int kk = 0; kk < BK; kk++) {
            ulonglong2 b0 = *(const ulonglong2*)&hs[kk][tx * 4];
            ulonglong2 b1 = *(const ulonglong2*)&hs[kk][64 + tx * 4];
            #pragma unroll
            for (int r = 0; r < 4; r++) {
                unsigned long long ap = pack_dup(Ps[ty * 4 + r][kk]);
                fma2(acc[r][0], ap, b0.x);
                fma2(acc[r][1], ap, b0.y);
                fma2(acc[r][2], ap, b1.x);
                fma2(acc[r][3], ap, b1.y);
            }
        }
        __syncthreads();
    }

    // --- normalize and write ---
    #pragma unroll
    for (int r = 0; r < 4; r++) {
        const int m = ty * 4 + r;
        const float zinv = 1.0f / Zs[m];
        float* op = out + (size_t)(m0 + m) * OUT_F;
        #pragma unroll
        for (int p = 0; p < 4; p++) {
            float lo, hi;
            unpack2(acc[r][p], lo, hi);
            int c = (p < 2) ? (tx * 4 + p * 2) : (64 + tx * 4 + (p - 2) * 2);
            op[c]     = lo * zinv;
            op[c + 1] = hi * zinv;
        }
    }
}

// ============================ launch =============================
extern "C" void kernel_launch(void* const* d_in, const int* in_sizes, int n_in,
                              void* d_out, int out_size) {
    // Map inputs robustly by element count (all four are distinct).
    const float *x = nullptr, *adj = nullptr, *W = nullptr, *a = nullptr;
    for (int i = 0; i < n_in; i++) {
        switch (in_sizes[i]) {
            case N_NODES * IN_F:        x   = (const float*)d_in[i]; break;
            case 67108864 /*8192^2*/:   adj = (const float*)d_in[i]; break;
            case IN_F * OUT_F:          W   = (const float*)d_in[i]; break;
            case 2 * OUT_F:             a   = (const float*)d_in[i]; break;
            default: break;
        }
    }
    if (!x)   x   = (const float*)d_in[0];
    if (!adj) adj = (const float*)d_in[1];
    if (!W)   W   = (const float*)d_in[2];
    if (!a)   a   = (const float*)d_in[3];
    float* out = (float*)d_out;

    h_gemm_kernel<<<N_NODES / 64, 256>>>(x, W);
    s_kernel<<<(N_NODES * 32) / 256, 256>>>(a);
    gat_main_kernel<<<N_NODES / 32, 128>>>(adj, out);
}

// round 3
// speedup vs baseline: 2.0470x; 2.0470x over previous
#include <cuda_runtime.h>
#include <cstdint>

#define N_NODES 8192
#define IN_F    256
#define OUT_F   128
#define ALPHA   0.2f
#define ITERS   (N_NODES / 32)

// ---------------- device scratch (no allocations allowed) ----------------
__device__ float g_h [N_NODES * OUT_F];
__device__ float g_s1[N_NODES], g_s2[N_NODES];
__device__ float g_E1[N_NODES], g_E2[N_NODES];
__device__ float g_F1[N_NODES], g_F2[N_NODES];

// ---------------- helpers ----------------
__device__ __forceinline__ uint32_t f2tf32(float f) {
    uint32_t r;
    asm("cvt.rna.tf32.f32 %0, %1;" : "=r"(r) : "f"(f));
    return r;
}

__device__ __forceinline__ void mma_tf32(float* d, const uint32_t* a, const uint32_t* b) {
    asm volatile(
        "mma.sync.aligned.m16n8k8.row.col.f32.tf32.tf32.f32 "
        "{%0,%1,%2,%3}, {%4,%5,%6,%7}, {%8,%9}, {%0,%1,%2,%3};"
        : "+f"(d[0]), "+f"(d[1]), "+f"(d[2]), "+f"(d[3])
        : "r"(a[0]), "r"(a[1]), "r"(a[2]), "r"(a[3]), "r"(b[0]), "r"(b[1]));
}

// ================= Kernel 1: h = x @ W  (8192x256 @ 256x128) =================
__global__ void __launch_bounds__(256) h_gemm_kernel(const float* __restrict__ x,
                                                     const float* __restrict__ W) {
    __shared__ float xs[64][32];
    __shared__ __align__(16) float Ws[32][OUT_F];

    const int tid = threadIdx.x;
    const int tx  = tid & 15;
    const int ty  = tid >> 4;
    const int m0  = blockIdx.x * 64;

    float acc[4][8];
    #pragma unroll
    for (int r = 0; r < 4; r++)
        #pragma unroll
        for (int c = 0; c < 8; c++) acc[r][c] = 0.f;

    for (int kt = 0; kt < IN_F; kt += 32) {
        #pragma unroll
        for (int i = tid; i < 64 * 32; i += 256)
            xs[i >> 5][i & 31] = x[(size_t)(m0 + (i >> 5)) * IN_F + kt + (i & 31)];
        #pragma unroll
        for (int i = tid * 4; i < 32 * OUT_F; i += 256 * 4)
            *(float4*)&Ws[i >> 7][i & 127] =
                *(const float4*)&W[(size_t)(kt + (i >> 7)) * OUT_F + (i & 127)];
        __syncthreads();

        #pragma unroll 8
        for (int kk = 0; kk < 32; kk++) {
            float b[8];
            *(float4*)&b[0] = *(const float4*)&Ws[kk][tx * 8];
            *(float4*)&b[4] = *(const float4*)&Ws[kk][tx * 8 + 4];
            #pragma unroll
            for (int r = 0; r < 4; r++) {
                float av = xs[ty * 4 + r][kk];
                #pragma unroll
                for (int c = 0; c < 8; c++) acc[r][c] = fmaf(av, b[c], acc[r][c]);
            }
        }
        __syncthreads();
    }

    #pragma unroll
    for (int r = 0; r < 4; r++)
        #pragma unroll
        for (int c = 0; c < 8; c++)
            g_h[(size_t)(m0 + ty * 4 + r) * OUT_F + tx * 8 + c] = acc[r][c];
}

// ====== Kernel 2: s1,s2 per node + factorized exponentials E/F ======
__global__ void __launch_bounds__(256) s_kernel(const float* __restrict__ a) {
    int node = (blockIdx.x * blockDim.x + threadIdx.x) >> 5;
    int lane = threadIdx.x & 31;
    if (node >= N_NODES) return;

    float s1 = 0.f, s2 = 0.f;
    #pragma unroll
    for (int c = lane; c < OUT_F; c += 32) {
        float hv = g_h[(size_t)node * OUT_F + c];
        s1 = fmaf(hv, __ldg(&a[c]),         s1);
        s2 = fmaf(hv, __ldg(&a[OUT_F + c]), s2);
    }
    #pragma unroll
    for (int o = 16; o; o >>= 1) {
        s1 += __shfl_xor_sync(0xffffffffu, s1, o);
        s2 += __shfl_xor_sync(0xffffffffu, s2, o);
    }
    if (lane == 0) {
        g_s1[node] = s1;               g_s2[node] = s2;
        g_E1[node] = expf(s1);         g_E2[node] = expf(s2);
        g_F1[node] = expf(ALPHA * s1); g_F2[node] = expf(ALPHA * s2);
    }
}

// ====== Kernel 3: mma.sync tf32 fused masked-softmax attention @ h ======
// CTA: 32 output rows x 128 cols. Stream K (j) in 32-wide tiles.
// Build P (factorized exp + adj mask) -> tf32 SMEM; B tile = g_h rows (tf32).
// 4 warps, each 32x32 warp tile via m16n8k8 tf32 mma.sync.
// Register prefetch of next tile's global data overlaps the MMA phase.
#define PS_STRIDE 36
#define HS_STRIDE 136

__global__ void __launch_bounds__(128) gat_mma_kernel(const float* __restrict__ adj,
                                                      float* __restrict__ out) {
    __shared__ uint32_t Ps[32 * PS_STRIDE];
    __shared__ uint32_t hs[32 * HS_STRIDE];
    __shared__ float Zs[32], s1s[32], E1s[32], F1s[32];

    const int tid  = threadIdx.x;
    const int lane = tid & 31;
    const int w    = tid >> 5;
    const int m0   = blockIdx.x * 32;

    if (tid < 32) {
        Zs[tid]  = 0.f;
        s1s[tid] = g_s1[m0 + tid];
        E1s[tid] = g_E1[m0 + tid];
        F1s[tid] = g_F1[m0 + tid];
    }
    __syncthreads();

    // build-role mapping
    const int br = tid >> 2;          // 0..31 : P row / h-tile row
    const int bc = (tid & 3) * 8;     // P col base (8 cols per thread)
    const int hc = (tid & 3) * 4;     // h col base (4-float chunks, stride 16)

    // mma-role mapping
    const int n0w = w * 32;
    const int gq  = lane >> 2;        // groupID
    const int tg  = lane & 3;         // threadID in group

    float acc[2][4][4];
    #pragma unroll
    for (int mt = 0; mt < 2; mt++)
        #pragma unroll
        for (int nt = 0; nt < 4; nt++)
            #pragma unroll
            for (int i = 0; i < 4; i++) acc[mt][nt][i] = 0.f;

    // prefetch registers
    float4 aj0, aj1, hv[8];
    float  s2v[8], E2v[8], F2v[8];

    // ---- prefetch tile 0 ----
    {
        const size_t arow = (size_t)(m0 + br) * N_NODES + bc;
        aj0 = __ldg((const float4*)&adj[arow]);
        aj1 = __ldg((const float4*)&adj[arow + 4]);
        #pragma unroll
        for (int q = 0; q < 8; q++)
            hv[q] = __ldg((const float4*)&g_h[(size_t)br * OUT_F + hc + 16 * q]);
        float4 t0, t1;
        t0 = __ldg((const float4*)&g_s2[bc]); t1 = __ldg((const float4*)&g_s2[bc + 4]);
        s2v[0]=t0.x; s2v[1]=t0.y; s2v[2]=t0.z; s2v[3]=t0.w;
        s2v[4]=t1.x; s2v[5]=t1.y; s2v[6]=t1.z; s2v[7]=t1.w;
        t0 = __ldg((const float4*)&g_E2[bc]); t1 = __ldg((const float4*)&g_E2[bc + 4]);
        E2v[0]=t0.x; E2v[1]=t0.y; E2v[2]=t0.z; E2v[3]=t0.w;
        E2v[4]=t1.x; E2v[5]=t1.y; E2v[6]=t1.z; E2v[7]=t1.w;
        t0 = __ldg((const float4*)&g_F2[bc]); t1 = __ldg((const float4*)&g_F2[bc + 4]);
        F2v[0]=t0.x; F2v[1]=t0.y; F2v[2]=t0.z; F2v[3]=t0.w;
        F2v[4]=t1.x; F2v[5]=t1.y; F2v[6]=t1.z; F2v[7]=t1.w;
    }

    const float s1v = s1s[br], E1v = E1s[br], F1v = F1s[br];

    for (int it = 0; it < ITERS; ++it) {
        // ---------- build P tile + h tile ----------
        {
            float av[8];
            av[0]=aj0.x; av[1]=aj0.y; av[2]=aj0.z; av[3]=aj0.w;
            av[4]=aj1.x; av[5]=aj1.y; av[6]=aj1.z; av[7]=aj1.w;
            float z = 0.f;
            uint32_t pp[8];
            #pragma unroll
            for (int q = 0; q < 8; q++) {
                float t = s1v + s2v[q];
                float e = (t >= 0.f) ? (E1v * E2v[q]) : (F1v * F2v[q]);
                float p = (av[q] > 0.f) ? e : 0.f;
                z += p;
                pp[q] = f2tf32(p);
            }
            *(uint4*)&Ps[br * PS_STRIDE + bc]     = make_uint4(pp[0], pp[1], pp[2], pp[3]);
            *(uint4*)&Ps[br * PS_STRIDE + bc + 4] = make_uint4(pp[4], pp[5], pp[6], pp[7]);
            z += __shfl_xor_sync(0xffffffffu, z, 1);
            z += __shfl_xor_sync(0xffffffffu, z, 2);
            if ((tid & 3) == 0) Zs[br] += z;

            #pragma unroll
            for (int q = 0; q < 8; q++) {
                uint4 hh;
                hh.x = f2tf32(hv[q].x); hh.y = f2tf32(hv[q].y);
                hh.z = f2tf32(hv[q].z); hh.w = f2tf32(hv[q].w);
                *(uint4*)&hs[br * HS_STRIDE + hc + 16 * q] = hh;
            }
        }
        __syncthreads();

        // ---------- prefetch next tile ----------
        if (it + 1 < ITERS) {
            const int j0 = (it + 1) * 32;
            const size_t arow = (size_t)(m0 + br) * N_NODES + j0 + bc;
            aj0 = __ldg((const float4*)&adj[arow]);
            aj1 = __ldg((const float4*)&adj[arow + 4]);
            #pragma unroll
            for (int q = 0; q < 8; q++)
                hv[q] = __ldg((const float4*)&g_h[(size_t)(j0 + br) * OUT_F + hc + 16 * q]);
            float4 t0, t1;
            t0 = __ldg((const float4*)&g_s2[j0 + bc]); t1 = __ldg((const float4*)&g_s2[j0 + bc + 4]);
            s2v[0]=t0.x; s2v[1]=t0.y; s2v[2]=t0.z; s2v[3]=t0.w;
            s2v[4]=t1.x; s2v[5]=t1.y; s2v[6]=t1.z; s2v[7]=t1.w;
            t0 = __ldg((const float4*)&g_E2[j0 + bc]); t1 = __ldg((const float4*)&g_E2[j0 + bc + 4]);
            E2v[0]=t0.x; E2v[1]=t0.y; E2v[2]=t0.z; E2v[3]=t0.w;
            E2v[4]=t1.x; E2v[5]=t1.y; E2v[6]=t1.z; E2v[7]=t1.w;
            t0 = __ldg((const float4*)&g_F2[j0 + bc]); t1 = __ldg((const float4*)&g_F2[j0 + bc + 4]);
            F2v[0]=t0.x; F2v[1]=t0.y; F2v[2]=t0.z; F2v[3]=t0.w;
            F2v[4]=t1.x; F2v[5]=t1.y; F2v[6]=t1.z; F2v[7]=t1.w;
        }

        // ---------- MMA phase ----------
        #pragma unroll
        for (int k8 = 0; k8 < 4; k8++) {
            uint32_t afr[2][4];
            #pragma unroll
            for (int mt = 0; mt < 2; mt++) {
                const int r = mt * 16 + gq;
                const int k = k8 * 8 + tg;
                afr[mt][0] = Ps[r * PS_STRIDE + k];
                afr[mt][1] = Ps[(r + 8) * PS_STRIDE + k];
                afr[mt][2] = Ps[r * PS_STRIDE + k + 4];
                afr[mt][3] = Ps[(r + 8) * PS_STRIDE + k + 4];
            }
            uint32_t bfr[4][2];
            #pragma unroll
            for (int nt = 0; nt < 4; nt++) {
                const int c = n0w + nt * 8 + gq;
                const int k = k8 * 8 + tg;
                bfr[nt][0] = hs[k * HS_STRIDE + c];
                bfr[nt][1] = hs[(k + 4) * HS_STRIDE + c];
            }
            #pragma unroll
            for (int mt = 0; mt < 2; mt++)
                #pragma unroll
                for (int nt = 0; nt < 4; nt++)
                    mma_tf32(acc[mt][nt], afr[mt], bfr[nt]);
        }
        __syncthreads();
    }

    // ---------- epilogue: normalize, store ----------
    float zinv[2][2];
    #pragma unroll
    for (int mt = 0; mt < 2; mt++) {
        zinv[mt][0] = 1.0f / Zs[mt * 16 + gq];
        zinv[mt][1] = 1.0f / Zs[mt * 16 + gq + 8];
    }
    #pragma unroll
    for (int mt = 0; mt < 2; mt++) {
        const int r = m0 + mt * 16 + gq;
        #pragma unroll
        for (int nt = 0; nt < 4; nt++) {
            const int c = n0w + nt * 8 + tg * 2;
            float2 v0 = make_float2(acc[mt][nt][0] * zinv[mt][0],
                                    acc[mt][nt][1] * zinv[mt][0]);
            float2 v1 = make_float2(acc[mt][nt][2] * zinv[mt][1],
                                    acc[mt][nt][3] * zinv[mt][1]);
            *(float2*)&out[(size_t)r * OUT_F + c]       = v0;
            *(float2*)&out[(size_t)(r + 8) * OUT_F + c] = v1;
        }
    }
}

// ============================ launch =============================
extern "C" void kernel_launch(void* const* d_in, const int* in_sizes, int n_in,
                              void* d_out, int out_size) {
    const float *x = nullptr, *adj = nullptr, *W = nullptr, *a = nullptr;
    for (int i = 0; i < n_in; i++) {
        switch (in_sizes[i]) {
            case N_NODES * IN_F:  x   = (const float*)d_in[i]; break;
            case 67108864:        adj = (const float*)d_in[i]; break;
            case IN_F * OUT_F:    W   = (const float*)d_in[i]; break;
            case 2 * OUT_F:       a   = (const float*)d_in[i]; break;
            default: break;
        }
    }
    if (!x)   x   = (const float*)d_in[0];
    if (!adj) adj = (const float*)d_in[1];
    if (!W)   W   = (const float*)d_in[2];
    if (!a)   a   = (const float*)d_in[3];
    float* out = (float*)d_out;

    h_gemm_kernel<<<N_NODES / 64, 256>>>(x, W);
    s_kernel<<<(N_NODES * 32) / 256, 256>>>(a);
    gat_mma_kernel<<<N_NODES / 32, 128>>>(adj, out);
}

// round 4
// speedup vs baseline: 3.1773x; 1.5522x over previous
#include <cuda_runtime.h>
#include <cstdint>

#define N_NODES 8192
#define IN_F    256
#define OUT_F   128
#define ALPHA   0.2f
#define ITERS   256            // 8192 / 32

// ---------------- device scratch (no allocations allowed) ----------------
__device__ float g_h [N_NODES * OUT_F];
__device__ float g_hr[N_NODES * OUT_F];   // tf32-rounded copy of h
__device__ float g_s1[N_NODES], g_s2[N_NODES];
__device__ float g_E1[N_NODES], g_E2[N_NODES];
__device__ float g_F1[N_NODES], g_F2[N_NODES];

// ---------------- helpers ----------------
__device__ __forceinline__ uint32_t f2tf32(float f) {
    uint32_t r;
    asm("cvt.rna.tf32.f32 %0, %1;" : "=r"(r) : "f"(f));
    return r;
}
__device__ __forceinline__ float tf32r(float f) {   // round-to-nearest tf32, as float
    uint32_t r = f2tf32(f);
    return __uint_as_float(r);
}
__device__ __forceinline__ void mma_tf32(float* d, const uint32_t* a, const uint32_t* b) {
    asm volatile(
        "mma.sync.aligned.m16n8k8.row.col.f32.tf32.tf32.f32 "
        "{%0,%1,%2,%3}, {%4,%5,%6,%7}, {%8,%9}, {%0,%1,%2,%3};"
        : "+f"(d[0]), "+f"(d[1]), "+f"(d[2]), "+f"(d[3])
        : "r"(a[0]), "r"(a[1]), "r"(a[2]), "r"(a[3]), "r"(b[0]), "r"(b[1]));
}
__device__ __forceinline__ uint32_t smem_u32(const void* p) {
    uint32_t r;
    asm("{ .reg .u64 t; cvta.to.shared.u64 t, %1; cvt.u32.u64 %0, t; }" : "=r"(r) : "l"(p));
    return r;
}
__device__ __forceinline__ void cpa16(uint32_t dst, const void* src) {
    asm volatile("cp.async.cg.shared.global [%0], [%1], 16;" :: "r"(dst), "l"(src) : "memory");
}
__device__ __forceinline__ void cpa_commit() {
    asm volatile("cp.async.commit_group;" ::: "memory");
}

// ================= Kernel 1: h = x @ W  (8192x256 @ 256x128) =================
// M tile 32 -> 256 CTAs (fills the chip), 256 threads.
__global__ void __launch_bounds__(256) h_gemm_kernel(const float* __restrict__ x,
                                                     const float* __restrict__ W) {
    __shared__ float xs[32][36];
    __shared__ __align__(16) float Ws[32][OUT_F];

    const int tid = threadIdx.x;
    const int tx  = tid & 31;   // 32 col groups of 4
    const int ty  = tid >> 5;   // 8 row groups of 4
    const int m0  = blockIdx.x * 32;

    float acc[4][4];
    #pragma unroll
    for (int r = 0; r < 4; r++)
        #pragma unroll
        for (int c = 0; c < 4; c++) acc[r][c] = 0.f;

    for (int kt = 0; kt < IN_F; kt += 32) {
        // x tile: 32 rows x 32 cols, one float4 per thread
        {
            const int row = tid >> 3, c = (tid & 7) * 4;
            *(float4*)&xs[row][c] = *(const float4*)&x[(size_t)(m0 + row) * IN_F + kt + c];
        }
        // W tile: 32 x 128, 4 float4 per thread
        #pragma unroll
        for (int q = 0; q < 4; q++) {
            const int idx = tid + 256 * q;
            const int row = idx >> 5, c = (idx & 31) * 4;
            *(float4*)&Ws[row][c] = *(const float4*)&W[(size_t)(kt + row) * OUT_F + c];
        }
        __syncthreads();

        #pragma unroll
        for (int kk = 0; kk < 32; kk++) {
            float4 b = *(const float4*)&Ws[kk][tx * 4];
            #pragma unroll
            for (int r = 0; r < 4; r++) {
                float av = xs[ty * 4 + r][kk];
                acc[r][0] = fmaf(av, b.x, acc[r][0]);
                acc[r][1] = fmaf(av, b.y, acc[r][1]);
                acc[r][2] = fmaf(av, b.z, acc[r][2]);
                acc[r][3] = fmaf(av, b.w, acc[r][3]);
            }
        }
        __syncthreads();
    }

    #pragma unroll
    for (int r = 0; r < 4; r++)
        *(float4*)&g_h[(size_t)(m0 + ty * 4 + r) * OUT_F + tx * 4] =
            make_float4(acc[r][0], acc[r][1], acc[r][2], acc[r][3]);
}

// ====== Kernel 2: s1,s2 + factorized exponentials + tf32-rounded h ======
__global__ void __launch_bounds__(256) s_kernel(const float* __restrict__ a) {
    int node = (blockIdx.x * blockDim.x + threadIdx.x) >> 5;
    int lane = threadIdx.x & 31;
    if (node >= N_NODES) return;

    float s1 = 0.f, s2 = 0.f;
    #pragma unroll
    for (int c = lane; c < OUT_F; c += 32) {
        float hv = g_h[(size_t)node * OUT_F + c];
        g_hr[(size_t)node * OUT_F + c] = tf32r(hv);
        s1 = fmaf(hv, __ldg(&a[c]),         s1);
        s2 = fmaf(hv, __ldg(&a[OUT_F + c]), s2);
    }
    #pragma unroll
    for (int o = 16; o; o >>= 1) {
        s1 += __shfl_xor_sync(0xffffffffu, s1, o);
        s2 += __shfl_xor_sync(0xffffffffu, s2, o);
    }
    if (lane == 0) {
        g_s1[node] = s1;               g_s2[node] = s2;
        g_E1[node] = expf(s1);         g_E2[node] = expf(s2);
        g_F1[node] = expf(ALPHA * s1); g_F2[node] = expf(ALPHA * s2);
    }
}

// ====== Kernel 3: pipelined mma.sync tf32 fused attention @ h ======
// CTA 64x128, 256 threads (8 warps, 2(M)x4(N), warp tile 32x32), K tile 32.
// cp.async 4-deep ring for adj + hr + s2/E2/F2. Build[i+1] overlaps MMA[i].
#define ADJ_BYTES 8192                 // 64*32*4
#define H_BYTES   17408                // 32*136*4  (stride 136 words)
#define SEF_BYTES 384                  // 3*32*4
#define PS_WORDS  (64 * 36)
#define OFF_ADJ 0
#define OFF_H   32768
#define OFF_SEF 102400
#define OFF_PS  103936
#define OFF_Z   122368
#define OFF_S1  122624
#define OFF_E1  122880
#define OFF_F1  123136
#define SMEM_SZ 123392

__device__ __forceinline__ void load_stage(uint32_t sbase, char* smem_unused,
                                           int st, int j0, int m0,
                                           const float* __restrict__ adj, int tid) {
    // adj: 64 rows x 128B -> 512 chunks of 16B, 2 per thread (contiguous dst)
    {
        const uint32_t adst = sbase + OFF_ADJ + st * ADJ_BYTES;
        const float* asrc = adj + (size_t)m0 * N_NODES + j0;
        const int c0 = tid * 2;
        cpa16(adst + (uint32_t)c0 * 16, asrc + (size_t)(c0 >> 3) * N_NODES + (c0 & 7) * 4);
        const int c1 = c0 + 1;
        cpa16(adst + (uint32_t)c1 * 16, asrc + (size_t)(c1 >> 3) * N_NODES + (c1 & 7) * 4);
    }
    // h: 32 rows x 512B data at 544B stride -> 1024 chunks, 4 per thread
    {
        const uint32_t hdst = sbase + OFF_H + st * H_BYTES;
        const float* hsrc = g_hr + (size_t)j0 * OUT_F;
        #pragma unroll
        for (int q = 0; q < 4; q++) {
            const int ch = tid * 4 + q;
            cpa16(hdst + (uint32_t)(ch >> 5) * 544 + (uint32_t)(ch & 31) * 16,
                  hsrc + (ch >> 5) * OUT_F + (ch & 31) * 4);
        }
    }
    // s2/E2/F2 strips: 3 x 128B = 24 chunks
    if (tid < 24) {
        const int arr = tid >> 3, ch = tid & 7;
        const float* s = (arr == 0) ? g_s2 : (arr == 1) ? g_E2 : g_F2;
        cpa16(sbase + OFF_SEF + st * SEF_BYTES + arr * 128 + ch * 16, s + j0 + ch * 4);
    }
}

__global__ void __launch_bounds__(256, 1) gat_mma_kernel(const float* __restrict__ adj,
                                                         float* __restrict__ out) {
    extern __shared__ __align__(16) char smem[];
    const uint32_t sbase = smem_u32(smem);

    float* Zs  = (float*)(smem + OFF_Z);
    float* s1s = (float*)(smem + OFF_S1);
    float* E1s = (float*)(smem + OFF_E1);
    float* F1s = (float*)(smem + OFF_F1);

    const int tid  = threadIdx.x;
    const int lane = tid & 31;
    const int w    = tid >> 5;
    const int m0   = blockIdx.x * 64;

    if (tid < 64) {
        Zs[tid]  = 0.f;
        s1s[tid] = g_s1[m0 + tid];
        E1s[tid] = g_E1[m0 + tid];
        F1s[tid] = g_F1[m0 + tid];
    }

    // issue stages 0,1,2
    load_stage(sbase, smem, 0, 0,  m0, adj, tid); cpa_commit();
    load_stage(sbase, smem, 1, 32, m0, adj, tid); cpa_commit();
    load_stage(sbase, smem, 2, 64, m0, adj, tid); cpa_commit();

    // build-role mapping: row br, 8 cols starting c0b
    const int br  = tid >> 2;
    const int c0b = (tid & 3) * 8;

    // mma-role mapping
    const int wm  = w & 1;          // 2 M-halves of 32 rows
    const int wn  = w >> 1;         // 4 N-quarters of 32 cols
    const int gq  = lane >> 2;
    const int tg  = lane & 3;

    asm volatile("cp.async.wait_group 2;" ::: "memory");
    __syncthreads();

    const float s1v = s1s[br], E1v = E1s[br], F1v = F1s[br];

    float acc[2][4][4];
    #pragma unroll
    for (int mt = 0; mt < 2; mt++)
        #pragma unroll
        for (int nt = 0; nt < 4; nt++)
            #pragma unroll
            for (int i = 0; i < 4; i++) acc[mt][nt][i] = 0.f;

    // ---- build P[0] into Ps buffer 0 ----
    {
        const float* adjS = (const float*)(smem + OFF_ADJ) + br * 32 + c0b;
        const float* sefS = (const float*)(smem + OFF_SEF);
        float av[8], s2v[8], E2v[8], F2v[8];
        *(float4*)&av[0]  = *(const float4*)adjS;
        *(float4*)&av[4]  = *(const float4*)(adjS + 4);
        *(float4*)&s2v[0] = *(const float4*)(sefS + c0b);
        *(float4*)&s2v[4] = *(const float4*)(sefS + c0b + 4);
        *(float4*)&E2v[0] = *(const float4*)(sefS + 32 + c0b);
        *(float4*)&E2v[4] = *(const float4*)(sefS + 32 + c0b + 4);
        *(float4*)&F2v[0] = *(const float4*)(sefS + 64 + c0b);
        *(float4*)&F2v[4] = *(const float4*)(sefS + 64 + c0b + 4);
        float z = 0.f;
        uint32_t pp[8];
        #pragma unroll
        for (int q = 0; q < 8; q++) {
            float t = s1v + s2v[q];
            float e = (t >= 0.f) ? (E1v * E2v[q]) : (F1v * F2v[q]);
            float p = (av[q] > 0.f) ? e : 0.f;
            z += p;
            pp[q] = f2tf32(p);
        }
        uint32_t* pd = (uint32_t*)(smem + OFF_PS) + br * 36 + c0b;
        *(uint4*)pd       = make_uint4(pp[0], pp[1], pp[2], pp[3]);
        *(uint4*)(pd + 4) = make_uint4(pp[4], pp[5], pp[6], pp[7]);
        z += __shfl_xor_sync(0xffffffffu, z, 1);
        z += __shfl_xor_sync(0xffffffffu, z, 2);
        if ((tid & 3) == 0) Zs[br] += z;
    }

    for (int it = 0; it < ITERS; ++it) {
        if (it < ITERS - 3) asm volatile("cp.async.wait_group 1;" ::: "memory");
        else                asm volatile("cp.async.wait_group 0;" ::: "memory");
        __syncthreads();

        if (it + 3 < ITERS) {
            load_stage(sbase, smem, (it + 3) & 3, (it + 3) * 32, m0, adj, tid);
            cpa_commit();
        }

        // ---- build P[it+1] into Ps[(it+1)&1] from stage (it+1)&3 ----
        if (it + 1 < ITERS) {
            const int st = (it + 1) & 3;
            const float* adjS = (const float*)(smem + OFF_ADJ + st * ADJ_BYTES) + br * 32 + c0b;
            const float* sefS = (const float*)(smem + OFF_SEF + st * SEF_BYTES);
            float av[8], s2v[8], E2v[8], F2v[8];
            *(float4*)&av[0]  = *(const float4*)adjS;
            *(float4*)&av[4]  = *(const float4*)(adjS + 4);
            *(float4*)&s2v[0] = *(const float4*)(sefS + c0b);
            *(float4*)&s2v[4] = *(const float4*)(sefS + c0b + 4);
            *(float4*)&E2v[0] = *(const float4*)(sefS + 32 + c0b);
            *(float4*)&E2v[4] = *(const float4*)(sefS + 32 + c0b + 4);
            *(float4*)&F2v[0] = *(const float4*)(sefS + 64 + c0b);
            *(float4*)&F2v[4] = *(const float4*)(sefS + 64 + c0b + 4);
            float z = 0.f;
            uint32_t pp[8];
            #pragma unroll
            for (int q = 0; q < 8; q++) {
                float t = s1v + s2v[q];
                float e = (t >= 0.f) ? (E1v * E2v[q]) : (F1v * F2v[q]);
                float p = (av[q] > 0.f) ? e : 0.f;
                z += p;
                pp[q] = f2tf32(p);
            }
            uint32_t* pd = (uint32_t*)(smem + OFF_PS + ((it + 1) & 1) * (PS_WORDS * 4))
                           + br * 36 + c0b;
            *(uint4*)pd       = make_uint4(pp[0], pp[1], pp[2], pp[3]);
            *(uint4*)(pd + 4) = make_uint4(pp[4], pp[5], pp[6], pp[7]);
            z += __shfl_xor_sync(0xffffffffu, z, 1);
            z += __shfl_xor_sync(0xffffffffu, z, 2);
            if ((tid & 3) == 0) Zs[br] += z;
        }

        // ---- MMA over P[it] x h[stage it&3] ----
        {
            const uint32_t* PsB = (const uint32_t*)(smem + OFF_PS + (it & 1) * (PS_WORDS * 4));
            const uint32_t* hB  = (const uint32_t*)(smem + OFF_H + (it & 3) * H_BYTES);
            #pragma unroll
            for (int k8 = 0; k8 < 4; k8++) {
                const int k = k8 * 8 + tg;
                uint32_t afr[2][4];
                #pragma unroll
                for (int mt = 0; mt < 2; mt++) {
                    const int r = wm * 32 + mt * 16 + gq;
                    afr[mt][0] = PsB[r * 36 + k];
                    afr[mt][1] = PsB[(r + 8) * 36 + k];
                    afr[mt][2] = PsB[r * 36 + k + 4];
                    afr[mt][3] = PsB[(r + 8) * 36 + k + 4];
                }
                uint32_t bfr[4][2];
                #pragma unroll
                for (int nt = 0; nt < 4; nt++) {
                    const int c = wn * 32 + nt * 8 + gq;
                    bfr[nt][0] = hB[k * 136 + c];
                    bfr[nt][1] = hB[(k + 4) * 136 + c];
                }
                #pragma unroll
                for (int mt = 0; mt < 2; mt++)
                    #pragma unroll
                    for (int nt = 0; nt < 4; nt++)
                        mma_tf32(acc[mt][nt], afr[mt], bfr[nt]);
            }
        }
    }
    __syncthreads();

    // ---- epilogue: normalize, store ----
    float zinv[2][2];
    #pragma unroll
    for (int mt = 0; mt < 2; mt++) {
        zinv[mt][0] = 1.0f / Zs[wm * 32 + mt * 16 + gq];
        zinv[mt][1] = 1.0f / Zs[wm * 32 + mt * 16 + gq + 8];
    }
    #pragma unroll
    for (int mt = 0; mt < 2; mt++) {
        const int r = m0 + wm * 32 + mt * 16 + gq;
        #pragma unroll
        for (int nt = 0; nt < 4; nt++) {
            const int c = wn * 32 + nt * 8 + tg * 2;
            *(float2*)&out[(size_t)r * OUT_F + c] =
                make_float2(acc[mt][nt][0] * zinv[mt][0], acc[mt][nt][1] * zinv[mt][0]);
            *(float2*)&out[(size_t)(r + 8) * OUT_F + c] =
                make_float2(acc[mt][nt][2] * zinv[mt][1], acc[mt][nt][3] * zinv[mt][1]);
        }
    }
}

// ============================ launch =============================
extern "C" void kernel_launch(void* const* d_in, const int* in_sizes, int n_in,
                              void* d_out, int out_size) {
    const float *x = nullptr, *adj = nullptr, *W = nullptr, *a = nullptr;
    for (int i = 0; i < n_in; i++) {
        switch (in_sizes[i]) {
            case N_NODES * IN_F:  x   = (const float*)d_in[i]; break;
            case 67108864:        adj = (const float*)d_in[i]; break;
            case IN_F * OUT_F:    W   = (const float*)d_in[i]; break;
            case 2 * OUT_F:       a   = (const float*)d_in[i]; break;
            default: break;
        }
    }
    if (!x)   x   = (const float*)d_in[0];
    if (!adj) adj = (const float*)d_in[1];
    if (!W)   W   = (const float*)d_in[2];
    if (!a)   a   = (const float*)d_in[3];
    float* out = (float*)d_out;

    h_gemm_kernel<<<N_NODES / 32, 256>>>(x, W);
    s_kernel<<<(N_NODES * 32) / 256, 256>>>(a);

    static int smem_set = 0;
    if (!smem_set) {
        cudaFuncSetAttribute(gat_mma_kernel, cudaFuncAttributeMaxDynamicSharedMemorySize, SMEM_SZ);
        smem_set = 1;
    }
    gat_mma_kernel<<<N_NODES / 64, 256, SMEM_SZ>>>(adj, out);
}

// round 5
// speedup vs baseline: 4.5231x; 1.4235x over previous
#include <cuda_runtime.h>
#include <cuda_fp16.h>
#include <cstdint>

#define N_NODES 8192
#define IN_F    256
#define OUT_F   128
#define ALPHA   0.2f
#define ITERS   256            // 8192 / 32

// ---------------- device scratch (no allocations allowed) ----------------
__device__ float  g_h [N_NODES * OUT_F];
__device__ __half g_hh[N_NODES * OUT_F];   // fp16 copy of h
__device__ float  g_s1[N_NODES], g_s2[N_NODES];
__device__ float  g_E1[N_NODES], g_E2[N_NODES];
__device__ float  g_F1[N_NODES], g_F2[N_NODES];

// ---------------- helpers ----------------
__device__ __forceinline__ uint32_t smem_u32(const void* p) {
    uint32_t r;
    asm("{ .reg .u64 t; cvta.to.shared.u64 t, %1; cvt.u32.u64 %0, t; }" : "=r"(r) : "l"(p));
    return r;
}
__device__ __forceinline__ void cpa16(uint32_t dst, const void* src) {
    asm volatile("cp.async.cg.shared.global [%0], [%1], 16;" :: "r"(dst), "l"(src) : "memory");
}
__device__ __forceinline__ void cpa_commit() {
    asm volatile("cp.async.commit_group;" ::: "memory");
}
__device__ __forceinline__ void ldm_x4(uint32_t* r, uint32_t addr) {
    asm volatile("ldmatrix.sync.aligned.m8n8.x4.shared.b16 {%0,%1,%2,%3}, [%4];"
                 : "=r"(r[0]), "=r"(r[1]), "=r"(r[2]), "=r"(r[3]) : "r"(addr));
}
__device__ __forceinline__ void ldm_x4_t(uint32_t* r, uint32_t addr) {
    asm volatile("ldmatrix.sync.aligned.m8n8.x4.trans.shared.b16 {%0,%1,%2,%3}, [%4];"
                 : "=r"(r[0]), "=r"(r[1]), "=r"(r[2]), "=r"(r[3]) : "r"(addr));
}
__device__ __forceinline__ void mma_f16(float* d, const uint32_t* a, const uint32_t* b) {
    asm volatile(
        "mma.sync.aligned.m16n8k16.row.col.f32.f16.f16.f32 "
        "{%0,%1,%2,%3}, {%4,%5,%6,%7}, {%8,%9}, {%0,%1,%2,%3};"
        : "+f"(d[0]), "+f"(d[1]), "+f"(d[2]), "+f"(d[3])
        : "r"(a[0]), "r"(a[1]), "r"(a[2]), "r"(a[3]), "r"(b[0]), "r"(b[1]));
}

// ================= Kernel 1: h = x @ W  (8192x256 @ 256x128) =================
__global__ void __launch_bounds__(256) h_gemm_kernel(const float* __restrict__ x,
                                                     const float* __restrict__ W) {
    __shared__ float xs[32][36];
    __shared__ __align__(16) float Ws[32][OUT_F];

    const int tid = threadIdx.x;
    const int tx  = tid & 31;
    const int ty  = tid >> 5;
    const int m0  = blockIdx.x * 32;

    float acc[4][4];
    #pragma unroll
    for (int r = 0; r < 4; r++)
        #pragma unroll
        for (int c = 0; c < 4; c++) acc[r][c] = 0.f;

    for (int kt = 0; kt < IN_F; kt += 32) {
        {
            const int row = tid >> 3, c = (tid & 7) * 4;
            *(float4*)&xs[row][c] = *(const float4*)&x[(size_t)(m0 + row) * IN_F + kt + c];
        }
        #pragma unroll
        for (int q = 0; q < 4; q++) {
            const int idx = tid + 256 * q;
            const int row = idx >> 5, c = (idx & 31) * 4;
            *(float4*)&Ws[row][c] = *(const float4*)&W[(size_t)(kt + row) * OUT_F + c];
        }
        __syncthreads();

        #pragma unroll
        for (int kk = 0; kk < 32; kk++) {
            float4 b = *(const float4*)&Ws[kk][tx * 4];
            #pragma unroll
            for (int r = 0; r < 4; r++) {
                float av = xs[ty * 4 + r][kk];
                acc[r][0] = fmaf(av, b.x, acc[r][0]);
                acc[r][1] = fmaf(av, b.y, acc[r][1]);
                acc[r][2] = fmaf(av, b.z, acc[r][2]);
                acc[r][3] = fmaf(av, b.w, acc[r][3]);
            }
        }
        __syncthreads();
    }

    #pragma unroll
    for (int r = 0; r < 4; r++)
        *(float4*)&g_h[(size_t)(m0 + ty * 4 + r) * OUT_F + tx * 4] =
            make_float4(acc[r][0], acc[r][1], acc[r][2], acc[r][3]);
}

// ====== Kernel 2: s1,s2 + factorized exponentials + fp16 h ======
__global__ void __launch_bounds__(256) s_kernel(const float* __restrict__ a) {
    int node = (blockIdx.x * blockDim.x + threadIdx.x) >> 5;
    int lane = threadIdx.x & 31;
    if (node >= N_NODES) return;

    float s1 = 0.f, s2 = 0.f;
    #pragma unroll
    for (int c = lane; c < OUT_F; c += 32) {
        float hv = g_h[(size_t)node * OUT_F + c];
        g_hh[(size_t)node * OUT_F + c] = __float2half_rn(hv);
        s1 = fmaf(hv, __ldg(&a[c]),         s1);
        s2 = fmaf(hv, __ldg(&a[OUT_F + c]), s2);
    }
    #pragma unroll
    for (int o = 16; o; o >>= 1) {
        s1 += __shfl_xor_sync(0xffffffffu, s1, o);
        s2 += __shfl_xor_sync(0xffffffffu, s2, o);
    }
    if (lane == 0) {
        g_s1[node] = s1;               g_s2[node] = s2;
        g_E1[node] = expf(s1);         g_E2[node] = expf(s2);
        g_F1[node] = expf(ALPHA * s1); g_F2[node] = expf(ALPHA * s2);
    }
}

// ====== Kernel 3: fp16 mma.sync fused attention, 6-deep cp.async ring ======
// CTA 64x128, 256 threads (8 warps: wm=w&1 M-half, wn=w>>2? -> w>>1 N-quarter).
// K tile 32. P (fp16) double-buffered @80B row stride; h (fp16) @272B stride.
#define STAGES   6
#define ADJ_ST   9216          // 64 rows * 144B (padded)
#define H_ST     8704          // 32 rows * 272B (padded)
#define SEF_ST   384
#define PS_ST    5120          // 64 rows * 80B
#define OFF_ADJ  0
#define OFF_H    55296         // 6*9216
#define OFF_SEF  107520        // +6*8704
#define OFF_PS   109824        // +6*384
#define OFF_Z    120064        // +2*5120
#define OFF_S1   120320
#define OFF_E1   120576
#define OFF_F1   120832
#define SMEM_SZ  121088

__device__ __forceinline__ void load_stage(uint32_t sbase, int st, int j0, int m0,
                                           const float* __restrict__ adj, int tid) {
    // adj: 64 rows x 128B data @144B stride -> 512 chunks, 2/thread
    {
        const uint32_t adst = sbase + OFF_ADJ + st * ADJ_ST;
        const float* asrc = adj + (size_t)m0 * N_NODES + j0;
        #pragma unroll
        for (int q = 0; q < 2; q++) {
            const int ch = tid * 2 + q;
            cpa16(adst + (uint32_t)(ch >> 3) * 144 + (uint32_t)(ch & 7) * 16,
                  asrc + (size_t)(ch >> 3) * N_NODES + (ch & 7) * 4);
        }
    }
    // h: 32 rows x 256B data @272B stride -> 512 chunks, 2/thread
    {
        const uint32_t hdst = sbase + OFF_H + st * H_ST;
        const __half* hsrc = g_hh + (size_t)j0 * OUT_F;
        #pragma unroll
        for (int q = 0; q < 2; q++) {
            const int ch = tid * 2 + q;
            cpa16(hdst + (uint32_t)(ch >> 4) * 272 + (uint32_t)(ch & 15) * 16,
                  hsrc + (ch >> 4) * OUT_F + (ch & 15) * 8);
        }
    }
    // s2/E2/F2 strips
    if (tid < 24) {
        const int arr = tid >> 3, ch = tid & 7;
        const float* s = (arr == 0) ? g_s2 : (arr == 1) ? g_E2 : g_F2;
        cpa16(sbase + OFF_SEF + st * SEF_ST + arr * 128 + ch * 16, s + j0 + ch * 4);
    }
}

__global__ void __launch_bounds__(256, 1) gat_mma_kernel(const float* __restrict__ adj,
                                                         float* __restrict__ out) {
    extern __shared__ __align__(16) char smem[];
    const uint32_t sbase = smem_u32(smem);

    float* Zs  = (float*)(smem + OFF_Z);
    float* s1s = (float*)(smem + OFF_S1);
    float* E1s = (float*)(smem + OFF_E1);
    float* F1s = (float*)(smem + OFF_F1);

    const int tid  = threadIdx.x;
    const int lane = tid & 31;
    const int w    = tid >> 5;
    const int m0   = blockIdx.x * 64;

    if (tid < 64) {
        Zs[tid]  = 0.f;
        s1s[tid] = g_s1[m0 + tid];
        E1s[tid] = g_E1[m0 + tid];
        F1s[tid] = g_F1[m0 + tid];
    }

    // prologue: issue stages 0..4
    #pragma unroll
    for (int s = 0; s < 5; s++) { load_stage(sbase, s, s * 32, m0, adj, tid); cpa_commit(); }

    // build-role mapping
    const int br  = tid >> 2;
    const int c0b = (tid & 3) * 8;

    // mma-role mapping
    const int wm  = w & 1;
    const int wn  = w >> 1;
    const int gq  = lane >> 2;
    const int tg  = lane & 3;

    // per-lane ldmatrix base offsets
    const uint32_t a_base = (uint32_t)(wm * 32 + (lane & 15)) * 80u + (uint32_t)(lane >> 4) * 16u;
    const uint32_t b_base = (uint32_t)(lane & 15) * 272u +
                            (uint32_t)(wn * 32 + (lane >> 4) * 8) * 2u;

    asm volatile("cp.async.wait_group 3;" ::: "memory");
    __syncthreads();

    const float s1v = s1s[br], E1v = E1s[br], F1v = F1s[br];

    float acc[2][4][4];
    #pragma unroll
    for (int mt = 0; mt < 2; mt++)
        #pragma unroll
        for (int nt = 0; nt < 4; nt++)
            #pragma unroll
            for (int i = 0; i < 4; i++) acc[mt][nt][i] = 0.f;

    // ---- build P[0] (stage 0 -> buf 0) ----
    {
        const float* adjS = (const float*)(smem + OFF_ADJ) + br * 36 + c0b;
        const float* sefS = (const float*)(smem + OFF_SEF);
        float av[8], s2v[8], E2v[8], F2v[8];
        *(float4*)&av[0]  = *(const float4*)adjS;
        *(float4*)&av[4]  = *(const float4*)(adjS + 4);
        *(float4*)&s2v[0] = *(const float4*)(sefS + c0b);
        *(float4*)&s2v[4] = *(const float4*)(sefS + c0b + 4);
        *(float4*)&E2v[0] = *(const float4*)(sefS + 32 + c0b);
        *(float4*)&E2v[4] = *(const float4*)(sefS + 32 + c0b + 4);
        *(float4*)&F2v[0] = *(const float4*)(sefS + 64 + c0b);
        *(float4*)&F2v[4] = *(const float4*)(sefS + 64 + c0b + 4);
        float z = 0.f, p[8];
        #pragma unroll
        for (int q = 0; q < 8; q++) {
            float t = s1v + s2v[q];
            float e = (t >= 0.f) ? (E1v * E2v[q]) : (F1v * F2v[q]);
            p[q] = (av[q] > 0.f) ? e : 0.f;
            z += p[q];
        }
        uint32_t pp[4];
        #pragma unroll
        for (int q = 0; q < 4; q++) {
            __half2 hh = __floats2half2_rn(p[q * 2], p[q * 2 + 1]);
            pp[q] = *(uint32_t*)&hh;
        }
        *(uint4*)(smem + OFF_PS + br * 80 + c0b * 2) = make_uint4(pp[0], pp[1], pp[2], pp[3]);
        z += __shfl_xor_sync(0xffffffffu, z, 1);
        z += __shfl_xor_sync(0xffffffffu, z, 2);
        if ((tid & 3) == 0) Zs[br] += z;
    }

    int st_mma = 0, st_bld = 1, st_ld = 5;

    for (int it = 0; it < ITERS; ++it) {
        if (it < ITERS - 5) asm volatile("cp.async.wait_group 3;" ::: "memory");
        else                asm volatile("cp.async.wait_group 0;" ::: "memory");
        __syncthreads();

        if (it + 5 < ITERS) {
            load_stage(sbase, st_ld, (it + 5) * 32, m0, adj, tid);
            cpa_commit();
            if (++st_ld == STAGES) st_ld = 0;
        }

        // ---- build P[it+1] into buf (it+1)&1 from stage st_bld ----
        if (it + 1 < ITERS) {
            const float* adjS = (const float*)(smem + OFF_ADJ + st_bld * ADJ_ST) + br * 36 + c0b;
            const float* sefS = (const float*)(smem + OFF_SEF + st_bld * SEF_ST);
            float av[8], s2v[8], E2v[8], F2v[8];
            *(float4*)&av[0]  = *(const float4*)adjS;
            *(float4*)&av[4]  = *(const float4*)(adjS + 4);
            *(float4*)&s2v[0] = *(const float4*)(sefS + c0b);
            *(float4*)&s2v[4] = *(const float4*)(sefS + c0b + 4);
            *(float4*)&E2v[0] = *(const float4*)(sefS + 32 + c0b);
            *(float4*)&E2v[4] = *(const float4*)(sefS + 32 + c0b + 4);
            *(float4*)&F2v[0] = *(const float4*)(sefS + 64 + c0b);
            *(float4*)&F2v[4] = *(const float4*)(sefS + 64 + c0b + 4);
            float z = 0.f, p[8];
            #pragma unroll
            for (int q = 0; q < 8; q++) {
                float t = s1v + s2v[q];
                float e = (t >= 0.f) ? (E1v * E2v[q]) : (F1v * F2v[q]);
                p[q] = (av[q] > 0.f) ? e : 0.f;
                z += p[q];
            }
            uint32_t pp[4];
            #pragma unroll
            for (int q = 0; q < 4; q++) {
                __half2 hh = __floats2half2_rn(p[q * 2], p[q * 2 + 1]);
                pp[q] = *(uint32_t*)&hh;
            }
            *(uint4*)(smem + OFF_PS + ((it + 1) & 1) * PS_ST + br * 80 + c0b * 2) =
                make_uint4(pp[0], pp[1], pp[2], pp[3]);
            z += __shfl_xor_sync(0xffffffffu, z, 1);
            z += __shfl_xor_sync(0xffffffffu, z, 2);
            if ((tid & 3) == 0) Zs[br] += z;
            if (++st_bld == STAGES) st_bld = 0;
        }

        // ---- MMA: P[it] (buf it&1) x h[stage st_mma] ----
        {
            const uint32_t pa = sbase + OFF_PS + (uint32_t)(it & 1) * PS_ST + a_base;
            const uint32_t hb = sbase + OFF_H + (uint32_t)st_mma * H_ST + b_base;

            uint32_t afr[2][2][4];   // [k16][mt]
            #pragma unroll
            for (int k16 = 0; k16 < 2; k16++)
                #pragma unroll
                for (int mt = 0; mt < 2; mt++)
                    ldm_x4(afr[k16][mt], pa + (uint32_t)mt * 1280u + (uint32_t)k16 * 32u);

            uint32_t bfr[2][2][4];   // [k16][np]
            #pragma unroll
            for (int k16 = 0; k16 < 2; k16++)
                #pragma unroll
                for (int np = 0; np < 2; np++)
                    ldm_x4_t(bfr[k16][np], hb + (uint32_t)k16 * 4352u + (uint32_t)np * 32u);

            #pragma unroll
            for (int k16 = 0; k16 < 2; k16++)
                #pragma unroll
                for (int mt = 0; mt < 2; mt++)
                    #pragma unroll
                    for (int nt = 0; nt < 4; nt++)
                        mma_f16(acc[mt][nt], afr[k16][mt],
                                &bfr[k16][nt >> 1][(nt & 1) * 2]);

            if (++st_mma == STAGES) st_mma = 0;
        }
    }
    __syncthreads();

    // ---- epilogue: normalize, store ----
    float zinv[2][2];
    #pragma unroll
    for (int mt = 0; mt < 2; mt++) {
        zinv[mt][0] = 1.0f / Zs[wm * 32 + mt * 16 + gq];
        zinv[mt][1] = 1.0f / Zs[wm * 32 + mt * 16 + gq + 8];
    }
    #pragma unroll
    for (int mt = 0; mt < 2; mt++) {
        const int r = m0 + wm * 32 + mt * 16 + gq;
        #pragma unroll
        for (int nt = 0; nt < 4; nt++) {
            const int c = wn * 32 + nt * 8 + tg * 2;
            *(float2*)&out[(size_t)r * OUT_F + c] =
                make_float2(acc[mt][nt][0] * zinv[mt][0], acc[mt][nt][1] * zinv[mt][0]);
            *(float2*)&out[(size_t)(r + 8) * OUT_F + c] =
                make_float2(acc[mt][nt][2] * zinv[mt][1], acc[mt][nt][3] * zinv[mt][1]);
        }
    }
}

// ============================ launch =============================
extern "C" void kernel_launch(void* const* d_in, const int* in_sizes, int n_in,
                              void* d_out, int out_size) {
    const float *x = nullptr, *adj = nullptr, *W = nullptr, *a = nullptr;
    for (int i = 0; i < n_in; i++) {
        switch (in_sizes[i]) {
            case N_NODES * IN_F:  x   = (const float*)d_in[i]; break;
            case 67108864:        adj = (const float*)d_in[i]; break;
            case IN_F * OUT_F:    W   = (const float*)d_in[i]; break;
            case 2 * OUT_F:       a   = (const float*)d_in[i]; break;
            default: break;
        }
    }
    if (!x)   x   = (const float*)d_in[0];
    if (!adj) adj = (const float*)d_in[1];
    if (!W)   W   = (const float*)d_in[2];
    if (!a)   a   = (const float*)d_in[3];
    float* out = (float*)d_out;

    h_gemm_kernel<<<N_NODES / 32, 256>>>(x, W);
    s_kernel<<<(N_NODES * 32) / 256, 256>>>(a);

    cudaFuncSetAttribute(gat_mma_kernel, cudaFuncAttributeMaxDynamicSharedMemorySize, SMEM_SZ);
    gat_mma_kernel<<<N_NODES / 64, 256, SMEM_SZ>>>(adj, out);
}

// round 6
// speedup vs baseline: 4.9721x; 1.0993x over previous
#include <cuda_runtime.h>
#include <cuda_fp16.h>
#include <cstdint>

#define N_NODES 8192
#define IN_F    256
#define OUT_F   128
#define ALPHA   0.2f
#define ITERS   256            // 8192 / 32

// ---------------- device scratch (no allocations allowed) ----------------
__device__ float  g_h [N_NODES * OUT_F];
__device__ __half g_hh[N_NODES * OUT_F];   // fp16 copy of h
__device__ float  g_s1[N_NODES], g_s2[N_NODES];
__device__ float  g_E1[N_NODES], g_E2[N_NODES];
__device__ float  g_F1[N_NODES], g_F2[N_NODES];

// ---------------- helpers ----------------
__device__ __forceinline__ uint32_t smem_u32(const void* p) {
    uint32_t r;
    asm("{ .reg .u64 t; cvta.to.shared.u64 t, %1; cvt.u32.u64 %0, t; }" : "=r"(r) : "l"(p));
    return r;
}
__device__ __forceinline__ void cpa16(uint32_t dst, const void* src) {
    asm volatile("cp.async.cg.shared.global [%0], [%1], 16;" :: "r"(dst), "l"(src) : "memory");
}
__device__ __forceinline__ void cpa_commit() {
    asm volatile("cp.async.commit_group;" ::: "memory");
}
__device__ __forceinline__ void ldm_x4(uint32_t* r, uint32_t addr) {
    asm volatile("ldmatrix.sync.aligned.m8n8.x4.shared.b16 {%0,%1,%2,%3}, [%4];"
                 : "=r"(r[0]), "=r"(r[1]), "=r"(r[2]), "=r"(r[3]) : "r"(addr));
}
__device__ __forceinline__ void ldm_x4_t(uint32_t* r, uint32_t addr) {
    asm volatile("ldmatrix.sync.aligned.m8n8.x4.trans.shared.b16 {%0,%1,%2,%3}, [%4];"
                 : "=r"(r[0]), "=r"(r[1]), "=r"(r[2]), "=r"(r[3]) : "r"(addr));
}
__device__ __forceinline__ void mma_f16(float* d, const uint32_t* a, const uint32_t* b) {
    asm volatile(
        "mma.sync.aligned.m16n8k16.row.col.f32.f16.f16.f32 "
        "{%0,%1,%2,%3}, {%4,%5,%6,%7}, {%8,%9}, {%0,%1,%2,%3};"
        : "+f"(d[0]), "+f"(d[1]), "+f"(d[2]), "+f"(d[3])
        : "r"(a[0]), "r"(a[1]), "r"(a[2]), "r"(a[3]), "r"(b[0]), "r"(b[1]));
}

// ================= Kernel 1: h = x @ W  (8192x256 @ 256x128) =================
__global__ void __launch_bounds__(256) h_gemm_kernel(const float* __restrict__ x,
                                                     const float* __restrict__ W) {
    __shared__ float xs[32][36];
    __shared__ __align__(16) float Ws[32][OUT_F];

    const int tid = threadIdx.x;
    const int tx  = tid & 31;
    const int ty  = tid >> 5;
    const int m0  = blockIdx.x * 32;

    float acc[4][4];
    #pragma unroll
    for (int r = 0; r < 4; r++)
        #pragma unroll
        for (int c = 0; c < 4; c++) acc[r][c] = 0.f;

    for (int kt = 0; kt < IN_F; kt += 32) {
        {
            const int row = tid >> 3, c = (tid & 7) * 4;
            *(float4*)&xs[row][c] = *(const float4*)&x[(size_t)(m0 + row) * IN_F + kt + c];
        }
        #pragma unroll
        for (int q = 0; q < 4; q++) {
            const int idx = tid + 256 * q;
            const int row = idx >> 5, c = (idx & 31) * 4;
            *(float4*)&Ws[row][c] = *(const float4*)&W[(size_t)(kt + row) * OUT_F + c];
        }
        __syncthreads();

        #pragma unroll
        for (int kk = 0; kk < 32; kk++) {
            float4 b = *(const float4*)&Ws[kk][tx * 4];
            #pragma unroll
            for (int r = 0; r < 4; r++) {
                float av = xs[ty * 4 + r][kk];
                acc[r][0] = fmaf(av, b.x, acc[r][0]);
                acc[r][1] = fmaf(av, b.y, acc[r][1]);
                acc[r][2] = fmaf(av, b.z, acc[r][2]);
                acc[r][3] = fmaf(av, b.w, acc[r][3]);
            }
        }
        __syncthreads();
    }

    #pragma unroll
    for (int r = 0; r < 4; r++)
        *(float4*)&g_h[(size_t)(m0 + ty * 4 + r) * OUT_F + tx * 4] =
            make_float4(acc[r][0], acc[r][1], acc[r][2], acc[r][3]);
}

// ====== Kernel 2: s1,s2 + factorized exponentials + fp16 h ======
__global__ void __launch_bounds__(256) s_kernel(const float* __restrict__ a) {
    int node = (blockIdx.x * blockDim.x + threadIdx.x) >> 5;
    int lane = threadIdx.x & 31;
    if (node >= N_NODES) return;

    float s1 = 0.f, s2 = 0.f;
    #pragma unroll
    for (int c = lane; c < OUT_F; c += 32) {
        float hv = g_h[(size_t)node * OUT_F + c];
        g_hh[(size_t)node * OUT_F + c] = __float2half_rn(hv);
        s1 = fmaf(hv, __ldg(&a[c]),         s1);
        s2 = fmaf(hv, __ldg(&a[OUT_F + c]), s2);
    }
    #pragma unroll
    for (int o = 16; o; o >>= 1) {
        s1 += __shfl_xor_sync(0xffffffffu, s1, o);
        s2 += __shfl_xor_sync(0xffffffffu, s2, o);
    }
    if (lane == 0) {
        g_s1[node] = s1;               g_s2[node] = s2;
        g_E1[node] = expf(s1);         g_E2[node] = expf(s2);
        g_F1[node] = expf(ALPHA * s1); g_F2[node] = expf(ALPHA * s2);
    }
}

// ====== Kernel 3: fp16 mma.sync fused attention, 512 threads, K-split ======
// CTA 64x128, 16 warps: wk (K 16-half) x wm (M 32-half) x wn (N 32-quarter).
// Each warp: 32x32 tile over K=16 per iter; wk partials merged in epilogue.
#define STAGES   6
#define ADJ_ST   9216          // 64 rows * 144B (padded)
#define H_ST     8704          // 32 rows * 272B (padded)
#define SEF_ST   384
#define PS_ST    5120          // 64 rows * 80B
#define OFF_ADJ  0
#define OFF_H    55296         // 6*9216
#define OFF_SEF  107520        // +6*8704
#define OFF_PS   109824        // +6*384
#define OFF_Z    120064        // +2*5120
#define OFF_S1   120320
#define OFF_E1   120576
#define OFF_F1   120832
#define SMEM_SZ  121088

__device__ __forceinline__ void load_stage(uint32_t sbase, int st, int j0, int m0,
                                           const float* __restrict__ adj, int tid) {
    // adj: 64 rows x 128B data @144B stride -> 512 chunks, 1/thread
    {
        const uint32_t adst = sbase + OFF_ADJ + st * ADJ_ST;
        const float* asrc = adj + (size_t)m0 * N_NODES + j0;
        cpa16(adst + (uint32_t)(tid >> 3) * 144 + (uint32_t)(tid & 7) * 16,
              asrc + (size_t)(tid >> 3) * N_NODES + (tid & 7) * 4);
    }
    // h: 32 rows x 256B data @272B stride -> 512 chunks, 1/thread
    {
        const uint32_t hdst = sbase + OFF_H + st * H_ST;
        const __half* hsrc = g_hh + (size_t)j0 * OUT_F;
        cpa16(hdst + (uint32_t)(tid >> 4) * 272 + (uint32_t)(tid & 15) * 16,
              hsrc + (tid >> 4) * OUT_F + (tid & 15) * 8);
    }
    // s2/E2/F2 strips
    if (tid < 24) {
        const int arr = tid >> 3, ch = tid & 7;
        const float* s = (arr == 0) ? g_s2 : (arr == 1) ? g_E2 : g_F2;
        cpa16(sbase + OFF_SEF + st * SEF_ST + arr * 128 + ch * 16, s + j0 + ch * 4);
    }
}

__global__ void __launch_bounds__(512, 1) gat_mma_kernel(const float* __restrict__ adj,
                                                         float* __restrict__ out) {
    extern __shared__ __align__(16) char smem[];
    const uint32_t sbase = smem_u32(smem);

    float* Zs  = (float*)(smem + OFF_Z);
    float* s1s = (float*)(smem + OFF_S1);
    float* E1s = (float*)(smem + OFF_E1);
    float* F1s = (float*)(smem + OFF_F1);

    const int tid  = threadIdx.x;
    const int lane = tid & 31;
    const int w    = tid >> 5;
    const int m0   = blockIdx.x * 64;

    if (tid < 64) {
        Zs[tid]  = 0.f;
        s1s[tid] = g_s1[m0 + tid];
        E1s[tid] = g_E1[m0 + tid];
        F1s[tid] = g_F1[m0 + tid];
    }

    // prologue: issue stages 0..4
    #pragma unroll
    for (int s = 0; s < 5; s++) { load_stage(sbase, s, s * 32, m0, adj, tid); cpa_commit(); }

    // build-role mapping: row br (0..63), 4 cols from c0b
    const int br  = tid >> 3;
    const int c0b = (tid & 7) * 4;

    // mma-role mapping
    const int wk  = w >> 3;          // K 16-half
    const int wm  = (w >> 2) & 1;    // M 32-half
    const int wn  = w & 3;           // N 32-quarter
    const int gq  = lane >> 2;
    const int tg  = lane & 3;

    // per-lane ldmatrix base offsets
    const uint32_t a_base = (uint32_t)(wm * 32 + (lane & 15)) * 80u + (uint32_t)wk * 32u
                          + (uint32_t)(lane >> 4) * 16u;
    const uint32_t b_base = (uint32_t)(wk * 16 + (lane & 15)) * 272u
                          + (uint32_t)(wn * 32 + (lane >> 4) * 8) * 2u;

    asm volatile("cp.async.wait_group 3;" ::: "memory");
    __syncthreads();

    const float s1v = s1s[br], E1v = E1s[br], F1v = F1s[br];

    float acc[2][4][4];
    #pragma unroll
    for (int mt = 0; mt < 2; mt++)
        #pragma unroll
        for (int nt = 0; nt < 4; nt++)
            #pragma unroll
            for (int i = 0; i < 4; i++) acc[mt][nt][i] = 0.f;

    // ---- build P[0] (stage 0 -> buf 0) ----
    {
        const float* adjS = (const float*)(smem + OFF_ADJ) + br * 36 + c0b;
        const float* sefS = (const float*)(smem + OFF_SEF);
        float4 av4 = *(const float4*)adjS;
        float4 s24 = *(const float4*)(sefS + c0b);
        float4 E24 = *(const float4*)(sefS + 32 + c0b);
        float4 F24 = *(const float4*)(sefS + 64 + c0b);
        float av[4]  = {av4.x, av4.y, av4.z, av4.w};
        float s2v[4] = {s24.x, s24.y, s24.z, s24.w};
        float E2v[4] = {E24.x, E24.y, E24.z, E24.w};
        float F2v[4] = {F24.x, F24.y, F24.z, F24.w};
        float z = 0.f, p[4];
        #pragma unroll
        for (int q = 0; q < 4; q++) {
            float t = s1v + s2v[q];
            float e = (t >= 0.f) ? (E1v * E2v[q]) : (F1v * F2v[q]);
            p[q] = (av[q] > 0.f) ? e : 0.f;
            z += p[q];
        }
        __half2 h0 = __floats2half2_rn(p[0], p[1]);
        __half2 h1 = __floats2half2_rn(p[2], p[3]);
        *(uint2*)(smem + OFF_PS + br * 80 + c0b * 2) =
            make_uint2(*(uint32_t*)&h0, *(uint32_t*)&h1);
        z += __shfl_xor_sync(0xffffffffu, z, 1);
        z += __shfl_xor_sync(0xffffffffu, z, 2);
        z += __shfl_xor_sync(0xffffffffu, z, 4);
        if ((tid & 7) == 0) Zs[br] += z;
    }

    int st_mma = 0, st_bld = 1, st_ld = 5;

    for (int it = 0; it < ITERS; ++it) {
        if (it < ITERS - 5) asm volatile("cp.async.wait_group 3;" ::: "memory");
        else                asm volatile("cp.async.wait_group 0;" ::: "memory");
        __syncthreads();

        if (it + 5 < ITERS) {
            load_stage(sbase, st_ld, (it + 5) * 32, m0, adj, tid);
            cpa_commit();
            if (++st_ld == STAGES) st_ld = 0;
        }

        // ---- build P[it+1] into buf (it+1)&1 from stage st_bld ----
        if (it + 1 < ITERS) {
            const float* adjS = (const float*)(smem + OFF_ADJ + st_bld * ADJ_ST) + br * 36 + c0b;
            const float* sefS = (const float*)(smem + OFF_SEF + st_bld * SEF_ST);
            float4 av4 = *(const float4*)adjS;
            float4 s24 = *(const float4*)(sefS + c0b);
            float4 E24 = *(const float4*)(sefS + 32 + c0b);
            float4 F24 = *(const float4*)(sefS + 64 + c0b);
            float av[4]  = {av4.x, av4.y, av4.z, av4.w};
            float s2v[4] = {s24.x, s24.y, s24.z, s24.w};
            float E2v[4] = {E24.x, E24.y, E24.z, E24.w};
            float F2v[4] = {F24.x, F24.y, F24.z, F24.w};
            float z = 0.f, p[4];
            #pragma unroll
            for (int q = 0; q < 4; q++) {
                float t = s1v + s2v[q];
                float e = (t >= 0.f) ? (E1v * E2v[q]) : (F1v * F2v[q]);
                p[q] = (av[q] > 0.f) ? e : 0.f;
                z += p[q];
            }
            __half2 h0 = __floats2half2_rn(p[0], p[1]);
            __half2 h1 = __floats2half2_rn(p[2], p[3]);
            *(uint2*)(smem + OFF_PS + ((it + 1) & 1) * PS_ST + br * 80 + c0b * 2) =
                make_uint2(*(uint32_t*)&h0, *(uint32_t*)&h1);
            z += __shfl_xor_sync(0xffffffffu, z, 1);
            z += __shfl_xor_sync(0xffffffffu, z, 2);
            z += __shfl_xor_sync(0xffffffffu, z, 4);
            if ((tid & 7) == 0) Zs[br] += z;
            if (++st_bld == STAGES) st_bld = 0;
        }

        // ---- MMA: P[it] (buf it&1) x h[stage st_mma], K-half wk ----
        {
            const uint32_t pa = sbase + OFF_PS + (uint32_t)(it & 1) * PS_ST + a_base;
            const uint32_t hb = sbase + OFF_H + (uint32_t)st_mma * H_ST + b_base;

            uint32_t afr[2][4];
            #pragma unroll
            for (int mt = 0; mt < 2; mt++)
                ldm_x4(afr[mt], pa + (uint32_t)mt * 1280u);

            uint32_t bfr[2][4];
            #pragma unroll
            for (int np = 0; np < 2; np++)
                ldm_x4_t(bfr[np], hb + (uint32_t)np * 32u);

            #pragma unroll
            for (int mt = 0; mt < 2; mt++)
                #pragma unroll
                for (int nt = 0; nt < 4; nt++)
                    mma_f16(acc[mt][nt], afr[mt], &bfr[nt >> 1][(nt & 1) * 2]);

            if (++st_mma == STAGES) st_mma = 0;
        }
    }
    __syncthreads();

    // ---- epilogue: merge wk partials through smem, normalize, store ----
    {
        const int tileid = wm * 4 + wn;
        float* mrg = (float*)(smem + OFF_ADJ) + tileid * (32 * 33);

        if (wk == 1) {
            #pragma unroll
            for (int mt = 0; mt < 2; mt++)
                #pragma unroll
                for (int nt = 0; nt < 4; nt++)
                    #pragma unroll
                    for (int i = 0; i < 4; i++) {
                        const int r = mt * 16 + gq + ((i >> 1) * 8);
                        const int c = nt * 8 + tg * 2 + (i & 1);
                        mrg[r * 33 + c] = acc[mt][nt][i];
                    }
        }
        __syncthreads();
        if (wk == 0) {
            #pragma unroll
            for (int mt = 0; mt < 2; mt++) {
                const int rl0 = mt * 16 + gq;
                const float zi0 = 1.0f / Zs[wm * 32 + rl0];
                const float zi1 = 1.0f / Zs[wm * 32 + rl0 + 8];
                const int r = m0 + wm * 32 + rl0;
                #pragma unroll
                for (int nt = 0; nt < 4; nt++) {
                    const int cl = nt * 8 + tg * 2;
                    const int c  = wn * 32 + cl;
                    float v0 = (acc[mt][nt][0] + mrg[rl0 * 33 + cl])       * zi0;
                    float v1 = (acc[mt][nt][1] + mrg[rl0 * 33 + cl + 1])   * zi0;
                    float v2 = (acc[mt][nt][2] + mrg[(rl0+8) * 33 + cl])   * zi1;
                    float v3 = (acc[mt][nt][3] + mrg[(rl0+8) * 33 + cl+1]) * zi1;
                    *(float2*)&out[(size_t)r * OUT_F + c]       = make_float2(v0, v1);
                    *(float2*)&out[(size_t)(r + 8) * OUT_F + c] = make_float2(v2, v3);
                }
            }
        }
    }
}

// ============================ launch =============================
extern "C" void kernel_launch(void* const* d_in, const int* in_sizes, int n_in,
                              void* d_out, int out_size) {
    const float *x = nullptr, *adj = nullptr, *W = nullptr, *a = nullptr;
    for (int i = 0; i < n_in; i++) {
        switch (in_sizes[i]) {
            case N_NODES * IN_F:  x   = (const float*)d_in[i]; break;
            case 67108864:        adj = (const float*)d_in[i]; break;
            case IN_F * OUT_F:    W   = (const float*)d_in[i]; break;
            case 2 * OUT_F:       a   = (const float*)d_in[i]; break;
            default: break;
        }
    }
    if (!x)   x   = (const float*)d_in[0];
    if (!adj) adj = (const float*)d_in[1];
    if (!W)   W   = (const float*)d_in[2];
    if (!a)   a   = (const float*)d_in[3];
    float* out = (float*)d_out;

    h_gemm_kernel<<<N_NODES / 32, 256>>>(x, W);
    s_kernel<<<(N_NODES * 32) / 256, 256>>>(a);

    cudaFuncSetAttribute(gat_mma_kernel, cudaFuncAttributeMaxDynamicSharedMemorySize, SMEM_SZ);
    gat_mma_kernel<<<N_NODES / 64, 512, SMEM_SZ>>>(adj, out);
}